// round 12
// baseline (speedup 1.0000x reference)
#include <cuda_runtime.h>
#include <cuda_fp16.h>
#include <cstdint>

// Problem constants
static constexpr int B_ = 4, N_ = 512, G_ = 8, KD = 64, V_ = 32000;
static constexpr int M_ROWS = B_ * N_;     // 2048
static constexpr int TM = 128, TN = 128, TK = 64;
static constexpr int MT = M_ROWS / TM;     // 16
static constexpr int NT = V_ / TN;         // 250
static constexpr int KS = (G_ * KD) / TK;  // 8 k-stages (one per group h)

// ---------------- device scratch ----------------
__device__ __align__(1024) __half g_Wh [(size_t)NT * KS * TN * TK];
__device__ __align__(1024) __half g_Ah [(size_t)MT * KS * TM * TK];
__device__ float g_part[(size_t)M_ROWS * NT];

// ---------------- helpers ----------------
__device__ __forceinline__ uint32_t smem_u32(const void* p) {
    uint32_t a;
    asm("{ .reg .u64 t; cvta.to.shared.u64 t, %1; cvt.u32.u64 %0, t; }" : "=r"(a) : "l"(p));
    return a;
}
__device__ __forceinline__ uint32_t swz128(uint32_t b) { return b ^ ((b >> 3) & 0x70); }

__device__ __forceinline__ void cp16(uint32_t dst, const void* src) {
    asm volatile("cp.async.cg.shared.global [%0], [%1], 16;" :: "r"(dst), "l"(src));
}
#define CP_COMMIT() asm volatile("cp.async.commit_group;" ::: "memory")
#define CP_WAIT1()  asm volatile("cp.async.wait_group 1;" ::: "memory")

#define LDSM4(r, addr) \
    asm volatile("ldmatrix.sync.aligned.m8n8.x4.shared.b16 {%0,%1,%2,%3}, [%4];" \
        : "=r"((r)[0]), "=r"((r)[1]), "=r"((r)[2]), "=r"((r)[3]) : "r"(addr))

#define MMA16816(c, a, b0, b1) \
    asm volatile("mma.sync.aligned.m16n8k16.row.col.f32.f16.f16.f32 " \
        "{%0,%1,%2,%3}, {%4,%5,%6,%7}, {%8,%9}, {%0,%1,%2,%3};" \
        : "+f"((c)[0]), "+f"((c)[1]), "+f"((c)[2]), "+f"((c)[3]) \
        : "r"((a)[0]), "r"((a)[1]), "r"((a)[2]), "r"((a)[3]), "r"(b0), "r"(b1))

// ---------------- kernel 1: gather psi -> blocked swizzled fp16 W ----------------
__global__ void gather_kernel(const int* __restrict__ perm32, const float* __restrict__ psi) {
    __shared__ int s64;
    if (threadIdx.x == 0) {
        int ok = 1;
        #pragma unroll
        for (int i = 0; i < 16; i++) ok &= (perm32[2 * i + 1] == 0);
        s64 = ok;
    }
    __syncthreads();
    const int is64 = s64;
    const long long* perm64 = (const long long*)perm32;

    const int lane = threadIdx.x & 31;
    int gw = (int)((blockIdx.x * blockDim.x + threadIdx.x) >> 5);
    const int nw = (int)((gridDim.x * blockDim.x) >> 5);

    for (int pair = gw; pair < V_ * G_; pair += nw) {
        const int v = pair >> 3;
        const int h = pair & 7;
        const int idx = is64 ? (int)perm64[(size_t)h * V_ + v] : perm32[(size_t)h * V_ + v];
        const float2 x = ((const float2*)(psi + (size_t)idx * KD))[lane];

        __half2 ph; ph.x = __float2half(x.x); ph.y = __float2half(x.y);

        const size_t blkB = ((size_t)(v >> 7) * KS + h) * (size_t)(TN * TK * 2); // 16 KB blocks
        const uint32_t off = swz128((uint32_t)((v & 127) * 128 + lane * 4));
        *(__half2*)((char*)g_Wh + blkB + off) = ph;
    }
}

// ---------------- kernel 2: phi -> blocked swizzled fp16 A ----------------
__global__ void phi_split_kernel(const float* __restrict__ phi) {
    const int lane = threadIdx.x & 31;
    int gw = (int)((blockIdx.x * blockDim.x + threadIdx.x) >> 5);
    const int nw = (int)((gridDim.x * blockDim.x) >> 5);

    for (int pair = gw; pair < M_ROWS * G_; pair += nw) {
        const int m = pair >> 3;
        const int h = pair & 7;
        const float2 x = ((const float2*)(phi + (size_t)m * (G_ * KD) + h * KD))[lane];

        __half2 ph; ph.x = __float2half(x.x); ph.y = __float2half(x.y);

        const size_t blkB = ((size_t)(m >> 7) * KS + h) * (size_t)(TM * TK * 2);
        const uint32_t off = swz128((uint32_t)((m & 127) * 128 + lane * 4));
        *(__half2*)((char*)g_Ah + blkB + off) = ph;
    }
}

// dummy keeps the ncu capture slot on the GEMM launch
__global__ void dummy_kernel() {}

// ---------------- kernel 3: HMMA GEMM, 4 warps @ 64x64 warp tile ----------------
// SMEM stage: A 16K | B 16K = 32 KB; 2 stages = 64 KB -> 3 CTAs/SM (192 KB)
static constexpr int STAGE_BYTES = 32768;
static constexpr int SMEM_DYN = 2 * STAGE_BYTES + 1024;   // + rowpart

__device__ __forceinline__ void load_stage(uint32_t st, int tid,
                                           const char* ah, const char* bh) {
    #pragma unroll
    for (int i = 0; i < 8; i++) {
        const int c = (tid + i * 128) * 16;
        cp16(st + 0     + c, ah + c);
        cp16(st + 16384 + c, bh + c);
    }
    CP_COMMIT();
}

__global__ __launch_bounds__(128, 3)
void gemm_kernel(float* __restrict__ out) {
    extern __shared__ char smem[];
    const uint32_t base = smem_u32(smem);
    float* rowpart = (float*)(smem + 2 * STAGE_BYTES);   // 128 rows x 2 n-warps

    const int tid  = threadIdx.x;
    const int wid  = tid >> 5;
    const int lane = tid & 31;
    const int wm   = wid & 1;   // 2 m-warps (64 rows each)
    const int wn   = wid >> 1;  // 2 n-warps (64 cols each)
    const int mtile = blockIdx.x;
    const int ntile = blockIdx.y;

    const char* ah = (const char*)g_Ah + (size_t)(mtile * KS) * 16384;
    const char* bh = (const char*)g_Wh + (size_t)(ntile * KS) * 16384;

    load_stage(base + 0 * STAGE_BYTES, tid, ah + 0 * 16384, bh + 0 * 16384);
    load_stage(base + 1 * STAGE_BYTES, tid, ah + 1 * 16384, bh + 1 * 16384);

    // ldmatrix address invariants (SW128)
    const int iA = lane >> 3, jA = lane & 7;
    const uint32_t aRowOff = (uint32_t)((wm * 64 + (iA & 1) * 8 + jA) * 128);
    const uint32_t aKbase  = (uint32_t)((iA >> 1) * 16);
    const uint32_t aswz    = (uint32_t)(jA << 4);
    const uint32_t bRowOff = (uint32_t)((wn * 64 + (iA >> 1) * 8 + jA) * 128);
    const uint32_t bKoff   = (uint32_t)((iA & 1) * 16);

    float c[4][8][4];
    #pragma unroll
    for (int a = 0; a < 4; a++)
        #pragma unroll
        for (int b = 0; b < 8; b++)
            #pragma unroll
            for (int d = 0; d < 4; d++) c[a][b][d] = 0.f;

    for (int s = 0; s < KS; s++) {
        CP_WAIT1();
        __syncthreads();
        const uint32_t buf = base + (uint32_t)(s & 1) * STAGE_BYTES;
        const uint32_t Ah = buf, Bh = buf + 16384;

        #pragma unroll
        for (int k0 = 0; k0 < 4; k0++) {
            uint32_t af[4][4];
            #pragma unroll
            for (int mf = 0; mf < 4; mf++) {
                const uint32_t addr = Ah + aRowOff + mf * 2048 + (((uint32_t)(k0 * 32) + aKbase) ^ aswz);
                LDSM4(af[mf], addr);
            }
            // two 32-col halves: keeps live B fragments at 8 regs
            #pragma unroll
            for (int half = 0; half < 2; half++) {
                uint32_t bf[2][4];
                #pragma unroll
                for (int q = 0; q < 2; q++) {
                    const uint32_t addr = Bh + bRowOff + (half * 2 + q) * 2048
                                        + (((uint32_t)(k0 * 32) + bKoff) ^ aswz);
                    LDSM4(bf[q], addr);
                }
                #pragma unroll
                for (int mf = 0; mf < 4; mf++) {
                    #pragma unroll
                    for (int nfh = 0; nfh < 4; nfh++) {
                        const int n2 = nfh >> 1, sub = (nfh & 1) * 2;
                        MMA16816(c[mf][half * 4 + nfh], af[mf], bf[n2][sub], bf[n2][sub + 1]);
                    }
                }
            }
        }
        __syncthreads();
        if (s + 2 < KS) {
            const uint32_t nb = base + (uint32_t)(s & 1) * STAGE_BYTES;
            load_stage(nb, tid, ah + (size_t)(s + 2) * 16384, bh + (size_t)(s + 2) * 16384);
        } else {
            CP_COMMIT();
        }
    }

    // -------- epilogue: exp + streaming stores + deterministic row partials --------
    const int rquad = lane >> 2;
    const int cpair = (lane & 3) * 2;
    const size_t ncolbase = (size_t)ntile * TN + wn * 64;
    const int mrowbase = mtile * TM + wm * 64;

    #pragma unroll
    for (int mf = 0; mf < 4; mf++) {
        #pragma unroll
        for (int rp = 0; rp < 2; rp++) {
            const int lrow = wm * 64 + mf * 16 + rp * 8 + rquad;
            const int grow = mrowbase + mf * 16 + rp * 8 + rquad;
            float s = 0.f;
            #pragma unroll
            for (int nf = 0; nf < 8; nf++) {
                const float e0 = __expf(c[mf][nf][rp * 2 + 0]);
                const float e1 = __expf(c[mf][nf][rp * 2 + 1]);
                s += e0 + e1;
                float2 w; w.x = e0; w.y = e1;
                __stcs((float2*)(out + (size_t)grow * V_ + ncolbase + nf * 8 + cpair), w);
            }
            s += __shfl_xor_sync(0xffffffffu, s, 1);
            s += __shfl_xor_sync(0xffffffffu, s, 2);
            if ((lane & 3) == 0) rowpart[lrow * 2 + wn] = s;
        }
    }
    __syncthreads();
    if (tid < 128) {
        const float t = rowpart[tid * 2 + 0] + rowpart[tid * 2 + 1];
        g_part[(size_t)(mtile * TM + tid) * NT + ntile] = t;
    }
}

// ---------------- kernel 4: deterministic row-sum reduce + scale ----------------
__global__ __launch_bounds__(256) void scale_kernel(float* __restrict__ out) {
    __shared__ float red[256];
    const int m = blockIdx.x;
    const int tid = threadIdx.x;
    red[tid] = (tid < NT) ? g_part[(size_t)m * NT + tid] : 0.f;
    __syncthreads();
    #pragma unroll
    for (int o = 128; o > 0; o >>= 1) {
        if (tid < o) red[tid] += red[tid + o];
        __syncthreads();
    }
    const float inv = 1.0f / red[0];
    float4* row = (float4*)(out + (size_t)m * V_);
    #pragma unroll 4
    for (int i = tid; i < V_ / 4; i += 256) {
        float4 v = __ldcs(row + i);
        v.x *= inv; v.y *= inv; v.z *= inv; v.w *= inv;
        __stcs(row + i, v);
    }
}

// ---------------- host launch ----------------
extern "C" void kernel_launch(void* const* d_in, const int* in_sizes, int n_in,
                              void* d_out, int out_size) {
    (void)in_sizes; (void)n_in; (void)out_size;
    const float* phi  = (const float*)d_in[0];
    const float* psi  = (const float*)d_in[1];
    const int*   perm = (const int*)d_in[2];
    float* out = (float*)d_out;

    cudaFuncSetAttribute(gemm_kernel, cudaFuncAttributeMaxDynamicSharedMemorySize, SMEM_DYN);

    gather_kernel<<<1024, 256>>>(perm, psi);
    phi_split_kernel<<<64, 256>>>(phi);
    dummy_kernel<<<1, 32>>>();                 // keeps ncu capture slot on gemm_kernel
    dim3 grid(MT, NT);                          // mtile fastest -> W ntile stays hot in L2
    gemm_kernel<<<grid, 128, SMEM_DYN>>>(out);
    scale_kernel<<<M_ROWS, 256>>>(out);
}

// round 13
// speedup vs baseline: 1.0001x; 1.0001x over previous
#include <cuda_runtime.h>
#include <cuda_fp16.h>
#include <cstdint>

// Problem constants
static constexpr int B_ = 4, N_ = 512, G_ = 8, KD = 64, V_ = 32000;
static constexpr int M_ROWS = B_ * N_;     // 2048
static constexpr int TM = 128, TN = 128, TK = 64;
static constexpr int MT = M_ROWS / TM;     // 16
static constexpr int NT = V_ / TN;         // 250
static constexpr int KS = (G_ * KD) / TK;  // 8 k-stages (one per group h)

// ---------------- device scratch ----------------
__device__ __align__(1024) __half g_Wh [(size_t)NT * KS * TN * TK];
__device__ __align__(1024) __half g_Ah [(size_t)MT * KS * TM * TK];
__device__ float g_part[(size_t)M_ROWS * NT];

// ---------------- helpers ----------------
__device__ __forceinline__ uint32_t smem_u32(const void* p) {
    uint32_t a;
    asm("{ .reg .u64 t; cvta.to.shared.u64 t, %1; cvt.u32.u64 %0, t; }" : "=r"(a) : "l"(p));
    return a;
}
__device__ __forceinline__ uint32_t swz128(uint32_t b) { return b ^ ((b >> 3) & 0x70); }

__device__ __forceinline__ void cp16(uint32_t dst, const void* src) {
    asm volatile("cp.async.cg.shared.global [%0], [%1], 16;" :: "r"(dst), "l"(src));
}
#define CP_COMMIT() asm volatile("cp.async.commit_group;" ::: "memory")
#define CP_WAIT2()  asm volatile("cp.async.wait_group 2;" ::: "memory")

#define LDSM4(r, addr) \
    asm volatile("ldmatrix.sync.aligned.m8n8.x4.shared.b16 {%0,%1,%2,%3}, [%4];" \
        : "=r"((r)[0]), "=r"((r)[1]), "=r"((r)[2]), "=r"((r)[3]) : "r"(addr))

#define MMA16816(c, a, b0, b1) \
    asm volatile("mma.sync.aligned.m16n8k16.row.col.f32.f16.f16.f32 " \
        "{%0,%1,%2,%3}, {%4,%5,%6,%7}, {%8,%9}, {%0,%1,%2,%3};" \
        : "+f"((c)[0]), "+f"((c)[1]), "+f"((c)[2]), "+f"((c)[3]) \
        : "r"((a)[0]), "r"((a)[1]), "r"((a)[2]), "r"((a)[3]), "r"(b0), "r"(b1))

// ---------------- kernel 1: gather psi -> blocked swizzled fp16 W ----------------
__global__ void gather_kernel(const int* __restrict__ perm32, const float* __restrict__ psi) {
    __shared__ int s64;
    if (threadIdx.x == 0) {
        int ok = 1;
        #pragma unroll
        for (int i = 0; i < 16; i++) ok &= (perm32[2 * i + 1] == 0);
        s64 = ok;
    }
    __syncthreads();
    const int is64 = s64;
    const long long* perm64 = (const long long*)perm32;

    const int lane = threadIdx.x & 31;
    int gw = (int)((blockIdx.x * blockDim.x + threadIdx.x) >> 5);
    const int nw = (int)((gridDim.x * blockDim.x) >> 5);

    for (int pair = gw; pair < V_ * G_; pair += nw) {
        const int v = pair >> 3;
        const int h = pair & 7;
        const int idx = is64 ? (int)perm64[(size_t)h * V_ + v] : perm32[(size_t)h * V_ + v];
        const float2 x = ((const float2*)(psi + (size_t)idx * KD))[lane];

        __half2 ph; ph.x = __float2half(x.x); ph.y = __float2half(x.y);

        const size_t blkB = ((size_t)(v >> 7) * KS + h) * (size_t)(TN * TK * 2); // 16 KB blocks
        const uint32_t off = swz128((uint32_t)((v & 127) * 128 + lane * 4));
        *(__half2*)((char*)g_Wh + blkB + off) = ph;
    }
}

// ---------------- kernel 2: phi -> blocked swizzled fp16 A ----------------
__global__ void phi_split_kernel(const float* __restrict__ phi) {
    const int lane = threadIdx.x & 31;
    int gw = (int)((blockIdx.x * blockDim.x + threadIdx.x) >> 5);
    const int nw = (int)((gridDim.x * blockDim.x) >> 5);

    for (int pair = gw; pair < M_ROWS * G_; pair += nw) {
        const int m = pair >> 3;
        const int h = pair & 7;
        const float2 x = ((const float2*)(phi + (size_t)m * (G_ * KD) + h * KD))[lane];

        __half2 ph; ph.x = __float2half(x.x); ph.y = __float2half(x.y);

        const size_t blkB = ((size_t)(m >> 7) * KS + h) * (size_t)(TM * TK * 2);
        const uint32_t off = swz128((uint32_t)((m & 127) * 128 + lane * 4));
        *(__half2*)((char*)g_Ah + blkB + off) = ph;
    }
}

// dummy keeps the ncu capture slot on the GEMM launch
__global__ void dummy_kernel() {}

// ---------------- kernel 3: HMMA GEMM (1-term fp16, sw-pipelined frags) ----------------
// SMEM stage: A 16K | B 16K = 32 KB; 3 stages = 96 KB -> 2 CTAs/SM
static constexpr int STAGE_BYTES = 32768;
static constexpr int SMEM_DYN = 3 * STAGE_BYTES;

__device__ __forceinline__ void load_stage(uint32_t st, int tid,
                                           const char* ah, const char* bh) {
    #pragma unroll
    for (int i = 0; i < 4; i++) {
        const int c = (tid + i * 256) * 16;
        cp16(st + 0     + c, ah + c);
        cp16(st + 16384 + c, bh + c);
    }
    CP_COMMIT();
}

__global__ __launch_bounds__(256, 2)
void gemm_kernel(float* __restrict__ out) {
    extern __shared__ char smem[];
    const uint32_t base = smem_u32(smem);

    const int tid  = threadIdx.x;
    const int wid  = tid >> 5;
    const int lane = tid & 31;
    const int wm   = wid & 1;   // 2 m-warps (64 rows each)
    const int wn   = wid >> 1;  // 4 n-warps (32 cols each)
    const int mtile = blockIdx.x;
    const int ntile = blockIdx.y;

    const char* ah = (const char*)g_Ah + (size_t)(mtile * KS) * 16384;
    const char* bh = (const char*)g_Wh + (size_t)(ntile * KS) * 16384;

    load_stage(base + 0 * STAGE_BYTES, tid, ah + 0 * 16384, bh + 0 * 16384);
    load_stage(base + 1 * STAGE_BYTES, tid, ah + 1 * 16384, bh + 1 * 16384);
    load_stage(base + 2 * STAGE_BYTES, tid, ah + 2 * 16384, bh + 2 * 16384);

    // ldmatrix address invariants (SW128)
    const int iA = lane >> 3, jA = lane & 7;
    const uint32_t aRowOff = (uint32_t)((wm * 64 + (iA & 1) * 8 + jA) * 128);
    const uint32_t aKbase  = (uint32_t)((iA >> 1) * 16);
    const uint32_t aswz    = (uint32_t)(jA << 4);
    const uint32_t bRowOff = (uint32_t)((wn * 32 + (iA >> 1) * 8 + jA) * 128);
    const uint32_t bKoff   = (uint32_t)((iA & 1) * 16);

    float c[4][4][4];
    #pragma unroll
    for (int a = 0; a < 4; a++)
        #pragma unroll
        for (int b = 0; b < 4; b++)
            #pragma unroll
            for (int d = 0; d < 4; d++) c[a][b][d] = 0.f;

    for (int s = 0; s < KS; s++) {
        CP_WAIT2();
        __syncthreads();
        const uint32_t buf = base + (uint32_t)(s % 3) * STAGE_BYTES;
        const uint32_t Ah = buf, Bh = buf + 16384;

        // fragment double-buffer: k0's regs filled while k0-1's MMAs run
        uint32_t af[2][4][4], bf[2][2][4];
        #pragma unroll
        for (int nf2 = 0; nf2 < 2; nf2++) {
            const uint32_t addr = Bh + bRowOff + nf2 * 2048 + (bKoff ^ aswz);
            LDSM4(bf[0][nf2], addr);
        }
        #pragma unroll
        for (int mf = 0; mf < 4; mf++) {
            const uint32_t addr = Ah + aRowOff + mf * 2048 + (aKbase ^ aswz);
            LDSM4(af[0][mf], addr);
        }

        #pragma unroll
        for (int k0 = 0; k0 < 4; k0++) {
            const int cur = k0 & 1;
            if (k0 < 3) {
                const int nxt = cur ^ 1;
                const uint32_t kb = (uint32_t)((k0 + 1) * 32);
                #pragma unroll
                for (int nf2 = 0; nf2 < 2; nf2++) {
                    const uint32_t addr = Bh + bRowOff + nf2 * 2048 + ((kb + bKoff) ^ aswz);
                    LDSM4(bf[nxt][nf2], addr);
                }
                #pragma unroll
                for (int mf = 0; mf < 4; mf++) {
                    const uint32_t addr = Ah + aRowOff + mf * 2048 + ((kb + aKbase) ^ aswz);
                    LDSM4(af[nxt][mf], addr);
                }
            }
            #pragma unroll
            for (int mf = 0; mf < 4; mf++) {
                #pragma unroll
                for (int nf = 0; nf < 4; nf++) {
                    const int n2 = nf >> 1, sub = (nf & 1) * 2;
                    MMA16816(c[mf][nf], af[cur][mf], bf[cur][n2][sub], bf[cur][n2][sub + 1]);
                }
            }
        }
        __syncthreads();
        if (s + 3 < KS) {
            const uint32_t nb = base + (uint32_t)((s + 3) % 3) * STAGE_BYTES;
            load_stage(nb, tid, ah + (size_t)(s + 3) * 16384, bh + (size_t)(s + 3) * 16384);
        } else {
            CP_COMMIT();
        }
    }

    // -------- epilogue: exp + streaming stores + deterministic row partials --------
    float* rowpart = (float*)smem;
    const int rquad = lane >> 2;
    const int cpair = (lane & 3) * 2;
    const size_t ncolbase = (size_t)ntile * TN + wn * 32;
    const int mrowbase = mtile * TM + wm * 64;

    #pragma unroll
    for (int mf = 0; mf < 4; mf++) {
        #pragma unroll
        for (int rp = 0; rp < 2; rp++) {
            const int lrow = wm * 64 + mf * 16 + rp * 8 + rquad;
            const int grow = mrowbase + mf * 16 + rp * 8 + rquad;
            float s = 0.f;
            #pragma unroll
            for (int nf = 0; nf < 4; nf++) {
                const float e0 = __expf(c[mf][nf][rp * 2 + 0]);
                const float e1 = __expf(c[mf][nf][rp * 2 + 1]);
                s += e0 + e1;
                float2 w; w.x = e0; w.y = e1;
                __stcs((float2*)(out + (size_t)grow * V_ + ncolbase + nf * 8 + cpair), w);
            }
            s += __shfl_xor_sync(0xffffffffu, s, 1);
            s += __shfl_xor_sync(0xffffffffu, s, 2);
            if ((lane & 3) == 0) rowpart[lrow * 4 + wn] = s;
        }
    }
    __syncthreads();
    if (tid < 128) {
        const float t = rowpart[tid * 4 + 0] + rowpart[tid * 4 + 1]
                      + rowpart[tid * 4 + 2] + rowpart[tid * 4 + 3];
        g_part[(size_t)(mtile * TM + tid) * NT + ntile] = t;
    }
}

// ---------------- kernel 4: deterministic row-sum reduce + scale ----------------
__global__ __launch_bounds__(256) void scale_kernel(float* __restrict__ out) {
    __shared__ float red[256];
    const int m = blockIdx.x;
    const int tid = threadIdx.x;
    red[tid] = (tid < NT) ? g_part[(size_t)m * NT + tid] : 0.f;
    __syncthreads();
    #pragma unroll
    for (int o = 128; o > 0; o >>= 1) {
        if (tid < o) red[tid] += red[tid + o];
        __syncthreads();
    }
    const float inv = 1.0f / red[0];
    float4* row = (float4*)(out + (size_t)m * V_);
    #pragma unroll 4
    for (int i = tid; i < V_ / 4; i += 256) {
        float4 v = __ldcs(row + i);
        v.x *= inv; v.y *= inv; v.z *= inv; v.w *= inv;
        __stcs(row + i, v);
    }
}

// ---------------- host launch ----------------
extern "C" void kernel_launch(void* const* d_in, const int* in_sizes, int n_in,
                              void* d_out, int out_size) {
    (void)in_sizes; (void)n_in; (void)out_size;
    const float* phi  = (const float*)d_in[0];
    const float* psi  = (const float*)d_in[1];
    const int*   perm = (const int*)d_in[2];
    float* out = (float*)d_out;

    cudaFuncSetAttribute(gemm_kernel, cudaFuncAttributeMaxDynamicSharedMemorySize, SMEM_DYN);

    gather_kernel<<<1024, 256>>>(perm, psi);
    phi_split_kernel<<<64, 256>>>(phi);
    dummy_kernel<<<1, 32>>>();                 // keeps ncu capture slot on gemm_kernel
    dim3 grid(MT, NT);                          // mtile fastest -> W ntile stays hot in L2
    gemm_kernel<<<grid, 256, SMEM_DYN>>>(out);
    scale_kernel<<<M_ROWS, 256>>>(out);
}

// round 14
// speedup vs baseline: 1.1089x; 1.1088x over previous
#include <cuda_runtime.h>
#include <cuda_fp16.h>
#include <cstdint>

// Problem constants
static constexpr int B_ = 4, N_ = 512, G_ = 8, KD = 64, V_ = 32000;
static constexpr int M_ROWS = B_ * N_;     // 2048
static constexpr int TM = 128, TN = 128, TK = 64;
static constexpr int MT = M_ROWS / TM;     // 16
static constexpr int NT = V_ / TN;         // 250
static constexpr int KS = (G_ * KD) / TK;  // 8 k-stages (one per group h)

// ---------------- device scratch ----------------
__device__ __align__(1024) __half g_Wh [(size_t)NT * KS * TN * TK];
__device__ __align__(1024) __half g_Ah [(size_t)MT * KS * TM * TK];
__device__ float g_part[(size_t)M_ROWS * NT];

// ---------------- helpers ----------------
__device__ __forceinline__ uint32_t smem_u32(const void* p) {
    uint32_t a;
    asm("{ .reg .u64 t; cvta.to.shared.u64 t, %1; cvt.u32.u64 %0, t; }" : "=r"(a) : "l"(p));
    return a;
}
__device__ __forceinline__ uint32_t swz128(uint32_t b) { return b ^ ((b >> 3) & 0x70); }

__device__ __forceinline__ void cp16(uint32_t dst, const void* src) {
    asm volatile("cp.async.cg.shared.global [%0], [%1], 16;" :: "r"(dst), "l"(src));
}
#define CP_COMMIT() asm volatile("cp.async.commit_group;" ::: "memory")
#define CP_WAIT2()  asm volatile("cp.async.wait_group 2;" ::: "memory")

#define LDSM4(r, addr) \
    asm volatile("ldmatrix.sync.aligned.m8n8.x4.shared.b16 {%0,%1,%2,%3}, [%4];" \
        : "=r"((r)[0]), "=r"((r)[1]), "=r"((r)[2]), "=r"((r)[3]) : "r"(addr))

#define MMA16816(c, a, b0, b1) \
    asm volatile("mma.sync.aligned.m16n8k16.row.col.f32.f16.f16.f32 " \
        "{%0,%1,%2,%3}, {%4,%5,%6,%7}, {%8,%9}, {%0,%1,%2,%3};" \
        : "+f"((c)[0]), "+f"((c)[1]), "+f"((c)[2]), "+f"((c)[3]) \
        : "r"((a)[0]), "r"((a)[1]), "r"((a)[2]), "r"((a)[3]), "r"(b0), "r"(b1))

// ---------------- kernel 1: fused gather(psi) + split(phi) -> blocked swizzled fp16 ----------------
__global__ void prep_kernel(const int* __restrict__ perm32, const float* __restrict__ psi,
                            const float* __restrict__ phi) {
    __shared__ int s64;
    if (threadIdx.x == 0) {
        int ok = 1;
        #pragma unroll
        for (int i = 0; i < 16; i++) ok &= (perm32[2 * i + 1] == 0);
        s64 = ok;
    }
    __syncthreads();
    const int is64 = s64;
    const long long* perm64 = (const long long*)perm32;

    const int lane = threadIdx.x & 31;
    const int gw0 = (int)((blockIdx.x * blockDim.x + threadIdx.x) >> 5);
    const int nw  = (int)((gridDim.x * blockDim.x) >> 5);

    // psi gather: 256K (v,h) pairs
    for (int pair = gw0; pair < V_ * G_; pair += nw) {
        const int v = pair >> 3;
        const int h = pair & 7;
        const int idx = is64 ? (int)perm64[(size_t)h * V_ + v] : perm32[(size_t)h * V_ + v];
        const float2 x = ((const float2*)(psi + (size_t)idx * KD))[lane];

        __half2 ph; ph.x = __float2half(x.x); ph.y = __float2half(x.y);

        const size_t blkB = ((size_t)(v >> 7) * KS + h) * (size_t)(TN * TK * 2); // 16 KB blocks
        const uint32_t off = swz128((uint32_t)((v & 127) * 128 + lane * 4));
        *(__half2*)((char*)g_Wh + blkB + off) = ph;
    }

    // phi convert: 16K (m,h) pairs (small; rides the gather tail)
    for (int pair = gw0; pair < M_ROWS * G_; pair += nw) {
        const int m = pair >> 3;
        const int h = pair & 7;
        const float2 x = ((const float2*)(phi + (size_t)m * (G_ * KD) + h * KD))[lane];

        __half2 ph; ph.x = __float2half(x.x); ph.y = __float2half(x.y);

        const size_t blkB = ((size_t)(m >> 7) * KS + h) * (size_t)(TM * TK * 2);
        const uint32_t off = swz128((uint32_t)((m & 127) * 128 + lane * 4));
        *(__half2*)((char*)g_Ah + blkB + off) = ph;
    }
}

// dummies keep the ncu capture slot on the GEMM launch (gemm is 4th of 5)
__global__ void dummy_kernel() {}
__global__ void dummy2_kernel() {}

// ---------------- kernel 2: HMMA GEMM (1-term fp16) + exp epilogue (R9, unchanged) ----------------
// SMEM stage: A 16K | B 16K = 32 KB; 3 stages = 96 KB -> 2 CTAs/SM
static constexpr int STAGE_BYTES = 32768;
static constexpr int SMEM_DYN = 3 * STAGE_BYTES;

__device__ __forceinline__ void load_stage(uint32_t st, int tid,
                                           const char* ah, const char* bh) {
    #pragma unroll
    for (int i = 0; i < 4; i++) {
        const int c = (tid + i * 256) * 16;
        cp16(st + 0     + c, ah + c);
        cp16(st + 16384 + c, bh + c);
    }
    CP_COMMIT();
}

__global__ __launch_bounds__(256, 2)
void gemm_kernel(float* __restrict__ out) {
    extern __shared__ char smem[];
    const uint32_t base = smem_u32(smem);

    const int tid  = threadIdx.x;
    const int wid  = tid >> 5;
    const int lane = tid & 31;
    const int wm   = wid & 1;   // 2 m-warps (64 rows each)
    const int wn   = wid >> 1;  // 4 n-warps (32 cols each)
    const int mtile = blockIdx.x;
    const int ntile = blockIdx.y;

    const char* ah = (const char*)g_Ah + (size_t)(mtile * KS) * 16384;
    const char* bh = (const char*)g_Wh + (size_t)(ntile * KS) * 16384;

    load_stage(base + 0 * STAGE_BYTES, tid, ah + 0 * 16384, bh + 0 * 16384);
    load_stage(base + 1 * STAGE_BYTES, tid, ah + 1 * 16384, bh + 1 * 16384);
    load_stage(base + 2 * STAGE_BYTES, tid, ah + 2 * 16384, bh + 2 * 16384);

    // ldmatrix address invariants (SW128)
    const int iA = lane >> 3, jA = lane & 7;
    const uint32_t aRowOff = (uint32_t)((wm * 64 + (iA & 1) * 8 + jA) * 128);
    const uint32_t aKbase  = (uint32_t)((iA >> 1) * 16);
    const uint32_t aswz    = (uint32_t)(jA << 4);
    const uint32_t bRowOff = (uint32_t)((wn * 32 + (iA >> 1) * 8 + jA) * 128);
    const uint32_t bKoff   = (uint32_t)((iA & 1) * 16);

    float c[4][4][4];
    #pragma unroll
    for (int a = 0; a < 4; a++)
        #pragma unroll
        for (int b = 0; b < 4; b++)
            #pragma unroll
            for (int d = 0; d < 4; d++) c[a][b][d] = 0.f;

    for (int s = 0; s < KS; s++) {
        CP_WAIT2();
        __syncthreads();
        const uint32_t buf = base + (uint32_t)(s % 3) * STAGE_BYTES;
        const uint32_t Ah = buf, Bh = buf + 16384;

        #pragma unroll
        for (int k0 = 0; k0 < 4; k0++) {
            uint32_t bf[2][4];
            #pragma unroll
            for (int nf2 = 0; nf2 < 2; nf2++) {
                const uint32_t addr = Bh + bRowOff + nf2 * 2048 + (((uint32_t)(k0 * 32) + bKoff) ^ aswz);
                LDSM4(bf[nf2], addr);
            }
            uint32_t af[4][4];
            #pragma unroll
            for (int mf = 0; mf < 4; mf++) {
                const uint32_t addr = Ah + aRowOff + mf * 2048 + (((uint32_t)(k0 * 32) + aKbase) ^ aswz);
                LDSM4(af[mf], addr);
            }
            #pragma unroll
            for (int mf = 0; mf < 4; mf++) {
                #pragma unroll
                for (int nf = 0; nf < 4; nf++) {
                    const int n2 = nf >> 1, sub = (nf & 1) * 2;
                    MMA16816(c[mf][nf], af[mf], bf[n2][sub], bf[n2][sub + 1]);
                }
            }
        }
        __syncthreads();
        if (s + 3 < KS) {
            const uint32_t nb = base + (uint32_t)((s + 3) % 3) * STAGE_BYTES;
            load_stage(nb, tid, ah + (size_t)(s + 3) * 16384, bh + (size_t)(s + 3) * 16384);
        } else {
            CP_COMMIT();
        }
    }

    // -------- epilogue: exp + streaming stores + deterministic row partials --------
    float* rowpart = (float*)smem;
    const int rquad = lane >> 2;
    const int cpair = (lane & 3) * 2;
    const size_t ncolbase = (size_t)ntile * TN + wn * 32;
    const int mrowbase = mtile * TM + wm * 64;

    #pragma unroll
    for (int mf = 0; mf < 4; mf++) {
        #pragma unroll
        for (int rp = 0; rp < 2; rp++) {
            const int lrow = wm * 64 + mf * 16 + rp * 8 + rquad;
            const int grow = mrowbase + mf * 16 + rp * 8 + rquad;
            float s = 0.f;
            #pragma unroll
            for (int nf = 0; nf < 4; nf++) {
                const float e0 = __expf(c[mf][nf][rp * 2 + 0]);
                const float e1 = __expf(c[mf][nf][rp * 2 + 1]);
                s += e0 + e1;
                float2 w; w.x = e0; w.y = e1;
                __stcs((float2*)(out + (size_t)grow * V_ + ncolbase + nf * 8 + cpair), w);
            }
            s += __shfl_xor_sync(0xffffffffu, s, 1);
            s += __shfl_xor_sync(0xffffffffu, s, 2);
            if ((lane & 3) == 0) rowpart[lrow * 4 + wn] = s;
        }
    }
    __syncthreads();
    if (tid < 128) {
        const float t = rowpart[tid * 4 + 0] + rowpart[tid * 4 + 1]
                      + rowpart[tid * 4 + 2] + rowpart[tid * 4 + 3];
        g_part[(size_t)(mtile * TM + tid) * NT + ntile] = t;
    }
}

// ---------------- kernel 3: scale, 2 CTAs per row (more DRAM-level parallelism) ----------------
static constexpr int Q4 = V_ / 4 / 2;   // float4s per half-row = 4000

__global__ __launch_bounds__(256) void scale_kernel(float* __restrict__ out) {
    __shared__ float red[256];
    const int m    = blockIdx.x >> 1;
    const int half = blockIdx.x & 1;
    const int tid  = threadIdx.x;

    red[tid] = (tid < NT) ? g_part[(size_t)m * NT + tid] : 0.f;
    __syncthreads();
    #pragma unroll
    for (int o = 128; o > 0; o >>= 1) {
        if (tid < o) red[tid] += red[tid + o];
        __syncthreads();
    }
    const float inv = 1.0f / red[0];

    float4* row = (float4*)(out + (size_t)m * V_) + half * Q4;
    #pragma unroll 4
    for (int i = tid; i < Q4; i += 256) {
        float4 v = __ldcs(row + i);
        v.x *= inv; v.y *= inv; v.z *= inv; v.w *= inv;
        __stcs(row + i, v);
    }
}

// ---------------- host launch ----------------
extern "C" void kernel_launch(void* const* d_in, const int* in_sizes, int n_in,
                              void* d_out, int out_size) {
    (void)in_sizes; (void)n_in; (void)out_size;
    const float* phi  = (const float*)d_in[0];
    const float* psi  = (const float*)d_in[1];
    const int*   perm = (const int*)d_in[2];
    float* out = (float*)d_out;

    cudaFuncSetAttribute(gemm_kernel, cudaFuncAttributeMaxDynamicSharedMemorySize, SMEM_DYN);

    prep_kernel<<<1024, 256>>>(perm, psi, phi);
    dummy_kernel<<<1, 32>>>();
    dummy2_kernel<<<1, 32>>>();                // gemm stays the 4th launch for ncu capture
    dim3 grid(MT, NT);                          // mtile fastest -> W ntile stays hot in L2
    gemm_kernel<<<grid, 256, SMEM_DYN>>>(out);
    scale_kernel<<<M_ROWS * 2, 256>>>(out);
}